// round 1
// baseline (speedup 1.0000x reference)
#include <cuda_runtime.h>
#include <math.h>

// Problem constants
#define L    4
#define H    512
#define BATCH 32
#define TT   1024
#define G4   2048        // 4*H gate width per layer
#define LH   2048        // L*H feedback width
#define JTOT 8192        // L * G4 total gate columns
#define NCTA 128
#define NTHR 256

// ---------------- static device scratch (no runtime allocation) ----------------
__device__ float g_Ut[L][LH][G4];          // U transposed: [l][k][j]   64MB
__device__ float g_xp[TT][BATCH][H];       // input projection           64MB
__device__ float g_h[L][BATCH][H];
__device__ float g_c[L][BATCH][H];
__device__ float g_part[4][BATCH][JTOT];   // U-GEMM partials [kg][b][J]  4MB
__device__ unsigned g_cnt = 0;
__device__ volatile unsigned g_gen = 0;

// ---------------- software grid barrier (all 128 CTAs co-resident) -------------
__device__ __forceinline__ void grid_sync()
{
    __syncthreads();
    if (threadIdx.x == 0) {
        unsigned g = g_gen;
        __threadfence();                        // release prior writes
        if (atomicAdd(&g_cnt, 1u) == NCTA - 1u) {
            g_cnt = 0;
            __threadfence();
            g_gen = g + 1u;
        } else {
            while (g_gen == g) { __nanosleep(64); }
        }
        __threadfence();                        // acquire others' writes
    }
    __syncthreads();
}

// ---------------- prep kernels ----------------

// Tiled transpose: g_Ut[l][k][j] = U[l][j][k]
__global__ void transpose_U(const float* __restrict__ U)
{
    __shared__ float tile[32][33];
    int l  = blockIdx.z;
    int jt = blockIdx.x * 32;
    int kt = blockIdx.y * 32;
    int tx = threadIdx.x, ty = threadIdx.y;      // 32 x 8
    #pragma unroll
    for (int r = 0; r < 32; r += 8)
        tile[ty + r][tx] = U[((size_t)(l * G4 + jt + ty + r)) * LH + kt + tx];
    __syncthreads();
    #pragma unroll
    for (int r = 0; r < 32; r += 8)
        g_Ut[l][kt + ty + r][jt + tx] = tile[tx][ty + r];
}

// Input projection: g_xp[t][b][h] = dot(x[t,b,:], lin_w[h,:]) + lin_b[h]
// Block handles 16 (t,b) pairs x all 512 h. 2048 blocks x 256 threads.
__global__ void xp_kernel(const float* __restrict__ x,
                          const float* __restrict__ lin_w,
                          const float* __restrict__ lin_b)
{
    __shared__ float xs[16][128];
    int tb0 = blockIdx.x * 16;
    int tid = threadIdx.x;
    #pragma unroll
    for (int r = 0; r < 8; ++r) {
        int e = r * 256 + tid;                   // 0..2047
        xs[e >> 7][e & 127] = x[(size_t)(tb0 + (e >> 7)) * 128 + (e & 127)];
    }
    __syncthreads();

    int h0 = tid, h1 = tid + 256;
    const float* w0 = lin_w + (size_t)h0 * 128;
    const float* w1 = lin_w + (size_t)h1 * 128;
    float acc0[16], acc1[16];
    #pragma unroll
    for (int p = 0; p < 16; ++p) { acc0[p] = 0.f; acc1[p] = 0.f; }

    for (int i = 0; i < 128; i += 4) {
        float4 a = *(const float4*)(w0 + i);
        float4 b = *(const float4*)(w1 + i);
        #pragma unroll
        for (int p = 0; p < 16; ++p) {
            float4 xv = *(const float4*)&xs[p][i];
            acc0[p] += a.x * xv.x + a.y * xv.y + a.z * xv.z + a.w * xv.w;
            acc1[p] += b.x * xv.x + b.y * xv.y + b.z * xv.z + b.w * xv.w;
        }
    }
    float b0 = lin_b[h0], b1 = lin_b[h1];
    float* xp = &g_xp[0][0][0];
    #pragma unroll
    for (int p = 0; p < 16; ++p) {
        size_t base = (size_t)(tb0 + p) * H;
        xp[base + h0] = acc0[p] + b0;
        xp[base + h1] = acc1[p] + b1;
    }
}

__global__ void init_hc(const float* __restrict__ h0, const float* __restrict__ c0)
{
    float* hp = &g_h[0][0][0];
    float* cp = &g_c[0][0][0];
    for (int i = blockIdx.x * blockDim.x + threadIdx.x; i < L * BATCH * H;
         i += gridDim.x * blockDim.x) {
        hp[i] = h0[i];
        cp[i] = c0[i];
    }
}

// ---------------- persistent recurrent kernel ----------------
__global__ void __launch_bounds__(NTHR, 1)
rnn_kernel(const float* __restrict__ W,
           const float* __restrict__ G,
           const float* __restrict__ mask_u,
           const float* __restrict__ mask_w,
           float* __restrict__ out)
{
    extern __shared__ float hx_s[];          // [32][512] = 64KB : this CTA's hx K-slice
    __shared__ float inp_s[4][H];            // C-phase layer input (4 batches)
    __shared__ float red[BATCH][8];
    __shared__ float ghs[BATCH];
    __shared__ float ex_tg[128];
    __shared__ float ex_so[128];

    const int c   = blockIdx.x;
    const int tid = threadIdx.x;

    // ---- B-phase (U-GEMM) identity: CTA = (kg, jg) ----
    const int kg  = c & 3;                   // K-slice (== feedback layer index)
    const int jg  = c >> 2;                  // 0..31, 256 gate columns each
    const int J0  = jg * 256;                // global gate column base
    const int lU  = J0 >> 11;                // layer owning these columns
    const int jl0 = J0 & 2047;
    const int warp = tid >> 5, lane = tid & 31;
    const int jb  = warp & 1, bbw = warp >> 1;
    const int b0w = bbw * 8;
    const int jcol = jl0 + jb * 128 + lane * 4;
    const int Jw   = J0 + jb * 128 + lane * 4;

    // ---- C-phase (W-chain + cell) identity: CTA = (bb, mb) ----
    const int c_b0 = (c >> 4) * 4;           // 8 batch-blocks of 4
    const int c_m0 = (c & 15) * 32;          // 16 m-blocks of 32
    const int qh = tid >> 7;                 // gate-half: 0 -> {i,f}, 1 -> {g,o}
    const int bl = (tid >> 5) & 3;
    const int ml = tid & 31;
    const int cb = c_b0 + bl;
    const int cm = c_m0 + ml;
    const int pid = bl * 32 + ml;

    // ---- A-phase identity ----
    const int ab  = tid >> 3;                // batch 0..31
    const int aks = (tid & 7) * 64;          // 64 k's per thread

    float* out_h = out;
    float* out_c = out + L * BATCH * H;
    float* out_g = out + 2 * L * BATCH * H;  // gates [L][B][T]

    for (int t = 0; t < TT; ++t) {
        // ======== A: build hx slice for layer kg into hx_s (redundant per CTA) ========
        {
            const float* hp = &g_h[kg][ab][0];
            const float* mu = &mask_u[(size_t)(kg * BATCH + ab) * H];
            const float* Gp = &G[kg * H];
            float s = 0.f;
            #pragma unroll 4
            for (int kk = 0; kk < 64; ++kk) {
                int k = aks + kk;
                float hm = hp[k] * mu[k];
                hx_s[ab * H + k] = hm;
                s += hm * Gp[k];
            }
            red[ab][tid & 7] = s;
            __syncthreads();
            if (tid < BATCH) {
                float ssum = 0.f;
                #pragma unroll
                for (int r = 0; r < 8; ++r) ssum += red[tid][r];
                float gh = 1.f / (1.f + expf(-ssum));
                ghs[tid] = gh;
                if (jg == 0)
                    out_g[(size_t)(kg * BATCH + tid) * TT + t] = gh;
            }
            __syncthreads();
            float gh = ghs[ab];
            #pragma unroll 4
            for (int kk = 0; kk < 64; ++kk)
                hx_s[ab * H + aks + kk] *= gh;
            __syncthreads();
        }

        // ======== B: g_part[kg][b][J] = sum_{k in slice} hx * Ut ========
        {
            float acc[8][4];
            #pragma unroll
            for (int i = 0; i < 8; ++i)
                #pragma unroll
                for (int q = 0; q < 4; ++q) acc[i][q] = 0.f;

            const float* Ub = &g_Ut[lU][kg * 512][jcol];
            #pragma unroll 2
            for (int k4 = 0; k4 < 512; k4 += 4) {
                float4 u0 = *(const float4*)(Ub + (k4 + 0) * G4);
                float4 u1 = *(const float4*)(Ub + (k4 + 1) * G4);
                float4 u2 = *(const float4*)(Ub + (k4 + 2) * G4);
                float4 u3 = *(const float4*)(Ub + (k4 + 3) * G4);
                #pragma unroll
                for (int i = 0; i < 8; ++i) {
                    float4 hv = *(const float4*)&hx_s[(b0w + i) * H + k4];
                    acc[i][0] += hv.x * u0.x + hv.y * u1.x + hv.z * u2.x + hv.w * u3.x;
                    acc[i][1] += hv.x * u0.y + hv.y * u1.y + hv.z * u2.y + hv.w * u3.y;
                    acc[i][2] += hv.x * u0.z + hv.y * u1.z + hv.z * u2.z + hv.w * u3.z;
                    acc[i][3] += hv.x * u0.w + hv.y * u1.w + hv.z * u2.w + hv.w * u3.w;
                }
            }
            #pragma unroll
            for (int i = 0; i < 8; ++i)
                *(float4*)&g_part[kg][b0w + i][Jw] =
                    make_float4(acc[i][0], acc[i][1], acc[i][2], acc[i][3]);
        }
        grid_sync();

        // ======== C: serial layer chain (W-GEMM + cell) ========
        for (int l = 0; l < L; ++l) {
            const float* src = (l == 0) ? &g_xp[t][0][0] : &g_h[l - 1][0][0];
            #pragma unroll
            for (int r = 0; r < 8; ++r) {
                int e  = r * NTHR + tid;        // 0..2047
                int bi = e >> 9, k = e & 511;
                inp_s[bi][k] = src[(size_t)(c_b0 + bi) * H + k] *
                               mask_w[(size_t)(l * BATCH + c_b0 + bi) * H + k];
            }
            __syncthreads();

            int q0 = qh * 2;
            const float* w0 = &W[((size_t)(l * G4 + q0 * 512 + cm)) * H];
            const float* w1 = w0 + (size_t)512 * H;
            int Ja = l * G4 + q0 * 512 + cm;
            int Jb2 = Ja + 512;
            float a0 = g_part[0][cb][Ja] + g_part[1][cb][Ja] +
                       g_part[2][cb][Ja] + g_part[3][cb][Ja];
            float a1 = g_part[0][cb][Jb2] + g_part[1][cb][Jb2] +
                       g_part[2][cb][Jb2] + g_part[3][cb][Jb2];

            #pragma unroll 2
            for (int k4 = 0; k4 < 512; k4 += 4) {
                float4 iv = *(const float4*)&inp_s[bl][k4];
                float4 wa = *(const float4*)(w0 + k4);
                float4 wb = *(const float4*)(w1 + k4);
                a0 += wa.x * iv.x + wa.y * iv.y + wa.z * iv.z + wa.w * iv.w;
                a1 += wb.x * iv.x + wb.y * iv.y + wb.z * iv.z + wb.w * iv.w;
            }

            if (qh == 1) {
                ex_tg[pid] = tanhf(a0);                    // tanh(gg)
                ex_so[pid] = 1.f / (1.f + expf(-a1));      // sigmoid(oo)
            }
            __syncthreads();
            if (qh == 0) {
                float si = 1.f / (1.f + expf(-a0));        // sigmoid(ii)
                float sf = 1.f / (1.f + expf(-a1));        // sigmoid(ff)
                float cold = g_c[l][cb][cm];
                float cn = sf * cold + si * ex_tg[pid];
                g_c[l][cb][cm] = cn;
                g_h[l][cb][cm] = ex_so[pid] * tanhf(cn);
            }
            grid_sync();
        }
    }

    // ======== final outputs ========
    const float* hp = &g_h[0][0][0];
    const float* cp = &g_c[0][0][0];
    for (int idx = c * NTHR + tid; idx < L * BATCH * H; idx += NCTA * NTHR) {
        out_h[idx] = hp[idx];
        out_c[idx] = cp[idx];
    }
}

// ---------------- launch ----------------
extern "C" void kernel_launch(void* const* d_in, const int* in_sizes, int n_in,
                              void* d_out, int out_size)
{
    const float* x      = (const float*)d_in[0];
    const float* lin_w  = (const float*)d_in[1];
    const float* lin_b  = (const float*)d_in[2];
    const float* W      = (const float*)d_in[3];
    const float* U      = (const float*)d_in[4];
    const float* G      = (const float*)d_in[5];
    const float* mask_u = (const float*)d_in[6];
    const float* mask_w = (const float*)d_in[7];
    const float* h0     = (const float*)d_in[8];
    const float* c0     = (const float*)d_in[9];
    float* out = (float*)d_out;

    (void)in_sizes; (void)n_in; (void)out_size;

    // U transpose to k-major
    dim3 tb(32, 8);
    dim3 tg(G4 / 32, LH / 32, L);
    transpose_U<<<tg, tb>>>(U);

    // input projection
    xp_kernel<<<(TT * BATCH) / 16, 256>>>(x, lin_w, lin_b);

    // state init
    init_hc<<<64, 256>>>(h0, c0);

    // persistent recurrent kernel (64KB dynamic SMEM)
    cudaFuncSetAttribute(rnn_kernel, cudaFuncAttributeMaxDynamicSharedMemorySize,
                         BATCH * H * (int)sizeof(float));
    rnn_kernel<<<NCTA, NTHR, BATCH * H * sizeof(float)>>>(W, G, mask_u, mask_w, out);
}

// round 2
// speedup vs baseline: 1.8148x; 1.8148x over previous
#include <cuda_runtime.h>
#include <math.h>

// Problem constants
#define L    4
#define H    512
#define BATCH 32
#define TT   1024
#define G4   2048        // 4*H gate width per layer
#define LH   2048        // L*H feedback width
#define JTOT 8192        // L * G4 total gate columns
#define NCTA 128
#define NTHR 512
#define ISTR 516         // padded inp_s row stride (floats)

// packed fp32x2 FMA: d = a*b + d  (two fp32 lanes per instruction)
#define FMA2(d, a, b) asm("fma.rn.f32x2 %0, %1, %2, %0;" : "+l"(d) : "l"(a), "l"(b))

__device__ __forceinline__ float lo32(unsigned long long v) { return __uint_as_float((unsigned)v); }
__device__ __forceinline__ float hi32(unsigned long long v) { return __uint_as_float((unsigned)(v >> 32)); }

// ---------------- static device scratch ----------------
// U k-pair interleaved: g_Up[l][k>>1][(j<<1)|(k&1)]
__device__ float g_Up[L][LH / 2][G4 * 2];          // 64MB
// W k-quad interleaved: g_Wz[l][k>>2][row][k&3]
__device__ float g_Wz[L][H / 4][G4][4];            // 16MB
__device__ float g_xp[TT][BATCH][H];               // 64MB
__device__ float g_h[L][BATCH][H];
__device__ float g_c[L][BATCH][H];
__device__ float g_part[4][BATCH][JTOT];           // U-GEMM partials
__device__ unsigned g_cnt = 0;
__device__ volatile unsigned g_gen = 0;

// ---------------- software grid barrier ----------------
__device__ __forceinline__ void grid_sync()
{
    __syncthreads();
    if (threadIdx.x == 0) {
        unsigned g = g_gen;
        __threadfence();
        if (atomicAdd(&g_cnt, 1u) == NCTA - 1u) {
            g_cnt = 0;
            __threadfence();
            g_gen = g + 1u;
        } else {
            while (g_gen == g) { __nanosleep(32); }
        }
        __threadfence();
    }
    __syncthreads();
}

// ---------------- prep kernels ----------------

// g_Up[l][kp][2j + (k&1)] = U[l][j][k]
__global__ void transpose_U(const float* __restrict__ U)
{
    __shared__ float tile[32][33];
    int l  = blockIdx.z;
    int jt = blockIdx.x * 32;
    int kt = blockIdx.y * 32;
    int tx = threadIdx.x, ty = threadIdx.y;      // 32 x 8
    #pragma unroll
    for (int r = 0; r < 32; r += 8)
        tile[ty + r][tx] = U[((size_t)(l * G4 + jt + ty + r)) * LH + kt + tx];
    __syncthreads();
    // write float2 {u(2kp,j), u(2kp+1,j)} at [l][kp][2j]
    int wtid = ty * 32 + tx;                     // 0..255
    int jl = wtid & 31;
    int kp0 = wtid >> 5;                         // 0..7
    #pragma unroll
    for (int r = 0; r < 2; ++r) {
        int kpl = kp0 + r * 8;                   // 0..15
        float2 v = make_float2(tile[jl][2 * kpl], tile[jl][2 * kpl + 1]);
        *(float2*)&g_Up[l][kt / 2 + kpl][(jt + jl) * 2] = v;
    }
}

// g_Wz[l][kq][row][0..3] = W[l][row][4kq..4kq+3]
__global__ void prep_W(const float* __restrict__ W)
{
    int l  = blockIdx.x >> 7;
    int kq = blockIdx.x & 127;
    for (int row = threadIdx.x; row < G4; row += blockDim.x) {
        float4 v = *(const float4*)&W[((size_t)(l * G4 + row)) * H + kq * 4];
        *(float4*)&g_Wz[l][kq][row][0] = v;
    }
}

// Input projection (unchanged)
__global__ void xp_kernel(const float* __restrict__ x,
                          const float* __restrict__ lin_w,
                          const float* __restrict__ lin_b)
{
    __shared__ float xs[16][128];
    int tb0 = blockIdx.x * 16;
    int tid = threadIdx.x;
    #pragma unroll
    for (int r = 0; r < 8; ++r) {
        int e = r * 256 + tid;
        xs[e >> 7][e & 127] = x[(size_t)(tb0 + (e >> 7)) * 128 + (e & 127)];
    }
    __syncthreads();

    int h0 = tid, h1 = tid + 256;
    const float* w0 = lin_w + (size_t)h0 * 128;
    const float* w1 = lin_w + (size_t)h1 * 128;
    float acc0[16], acc1[16];
    #pragma unroll
    for (int p = 0; p < 16; ++p) { acc0[p] = 0.f; acc1[p] = 0.f; }

    for (int i = 0; i < 128; i += 4) {
        float4 a = *(const float4*)(w0 + i);
        float4 b = *(const float4*)(w1 + i);
        #pragma unroll
        for (int p = 0; p < 16; ++p) {
            float4 xv = *(const float4*)&xs[p][i];
            acc0[p] += a.x * xv.x + a.y * xv.y + a.z * xv.z + a.w * xv.w;
            acc1[p] += b.x * xv.x + b.y * xv.y + b.z * xv.z + b.w * xv.w;
        }
    }
    float b0 = lin_b[h0], b1 = lin_b[h1];
    float* xp = &g_xp[0][0][0];
    #pragma unroll
    for (int p = 0; p < 16; ++p) {
        size_t base = (size_t)(tb0 + p) * H;
        xp[base + h0] = acc0[p] + b0;
        xp[base + h1] = acc1[p] + b1;
    }
}

__global__ void init_hc(const float* __restrict__ h0, const float* __restrict__ c0)
{
    float* hp = &g_h[0][0][0];
    float* cp = &g_c[0][0][0];
    for (int i = blockIdx.x * blockDim.x + threadIdx.x; i < L * BATCH * H;
         i += gridDim.x * blockDim.x) {
        hp[i] = h0[i];
        cp[i] = c0[i];
    }
}

// ---------------- persistent recurrent kernel ----------------
__global__ void __launch_bounds__(NTHR, 1)
rnn_kernel(const float* __restrict__ G,
           const float* __restrict__ mask_u,
           const float* __restrict__ mask_w,
           float* __restrict__ out)
{
    extern __shared__ float sm[];                // union: hx[32][512] (B) / inp[32][516] (C)
    __shared__ float red[BATCH][16];
    __shared__ float ghs[BATCH];
    __shared__ float sm_g[16][33];               // gate exchange (activated)

    const int c    = blockIdx.x;
    const int tid  = threadIdx.x;
    const int warp = tid >> 5;
    const int lane = tid & 31;

    // ---- B-phase identity: CTA = (kg, jg); warp = (bw, jw) ----
    const int kg  = c & 3;
    const int jg  = c >> 2;                      // 0..31
    const int J0  = jg * 256;
    const int lU  = J0 >> 11;
    const int jl0 = J0 & 2047;
    const int jw  = warp & 3;
    const int bw  = warp >> 2;
    const int b0w = bw * 8;
    const int c2  = jl0 + jw * 64 + lane * 2;    // within-layer column (pairs)
    const int Jw  = J0 + jw * 64 + lane * 2;     // global column

    // ---- C-phase identity: CTA = mb (h-col block of 4); warp = b-pair ----
    const int mb   = c;                          // 0..127
    const int cb   = warp * 2 + (lane & 1);      // batch 0..31
    const int r16  = lane >> 1;                  // 0..15
    const int q    = r16 >> 2;                   // gate 0..3 (i,f,g,o)
    const int ms   = r16 & 3;
    const int mg   = mb * 4 + ms;                // h index 0..511
    const int crow = q * 512 + mg;               // gate row within layer

    // ---- A-phase identity ----
    const int ab  = tid >> 4;                    // batch 0..31
    const int aks = (tid & 15) * 32;

    float* out_h = out;
    float* out_c = out + L * BATCH * H;
    float* out_g = out + 2 * L * BATCH * H;      // [L][B][T]

    for (int t = 0; t < TT; ++t) {
        // ======== A: build hx slice (layer kg) into sm, stride 512 ========
        {
            const float* hp = &g_h[kg][ab][0];
            const float* mu = &mask_u[(size_t)(kg * BATCH + ab) * H];
            const float* Gp = &G[kg * H];
            float s = 0.f;
            #pragma unroll 4
            for (int kk = 0; kk < 32; ++kk) {
                int k = aks + kk;
                float hm = hp[k] * mu[k];
                sm[ab * 512 + k] = hm;
                s += hm * Gp[k];
            }
            red[ab][tid & 15] = s;
            __syncthreads();
            if (tid < BATCH) {
                float ssum = 0.f;
                #pragma unroll
                for (int r = 0; r < 16; ++r) ssum += red[tid][r];
                float gh = 1.f / (1.f + expf(-ssum));
                ghs[tid] = gh;
                if (jg == 0)
                    out_g[(size_t)(kg * BATCH + tid) * TT + t] = gh;
            }
            __syncthreads();
            float gh = ghs[ab];
            #pragma unroll 4
            for (int kk = 0; kk < 32; ++kk)
                sm[ab * 512 + aks + kk] *= gh;
            __syncthreads();
        }

        // ======== B: U-GEMM partials via fma.rn.f32x2 ========
        {
            unsigned long long acc[8][2];
            #pragma unroll
            for (int i = 0; i < 8; ++i) { acc[i][0] = 0ull; acc[i][1] = 0ull; }

            const float* Ub = &g_Up[lU][kg * 256][c2 * 2];
            #pragma unroll 2
            for (int kp2 = 0; kp2 < 128; ++kp2) {
                ulonglong2 ua = *(const ulonglong2*)(Ub + (size_t)(2 * kp2) * 4096);
                ulonglong2 ub = *(const ulonglong2*)(Ub + (size_t)(2 * kp2 + 1) * 4096);
                #pragma unroll
                for (int i = 0; i < 8; ++i) {
                    ulonglong2 hv = *(const ulonglong2*)&sm[(b0w + i) * 512 + 4 * kp2];
                    FMA2(acc[i][0], hv.x, ua.x);
                    FMA2(acc[i][1], hv.x, ua.y);
                    FMA2(acc[i][0], hv.y, ub.x);
                    FMA2(acc[i][1], hv.y, ub.y);
                }
            }
            #pragma unroll
            for (int i = 0; i < 8; ++i) {
                float2 v = make_float2(lo32(acc[i][0]) + hi32(acc[i][0]),
                                       lo32(acc[i][1]) + hi32(acc[i][1]));
                *(float2*)&g_part[kg][b0w + i][Jw] = v;
            }
        }
        grid_sync();

        // ======== C: serial layer chain ========
        for (int l = 0; l < L; ++l) {
            // build masked inp for all 32 batches (stride ISTR)
            {
                const float* src = (l == 0) ? &g_xp[t][0][0] : &g_h[l - 1][0][0];
                const float* mw  = &mask_w[(size_t)l * BATCH * H];
                #pragma unroll
                for (int r = 0; r < 32; ++r) {
                    int e  = r * NTHR + tid;     // 0..16383
                    int bi = e >> 9, k = e & 511;
                    sm[bi * ISTR + k] = src[(size_t)bi * H + k] * mw[(size_t)bi * H + k];
                }
            }
            __syncthreads();

            // gate dot: row crow, batch cb, K=512 via fma2
            unsigned long long accA = 0ull, accB = 0ull;
            const float* Wp  = &g_Wz[l][0][crow][0];
            const float* ibp = &sm[cb * ISTR];
            #pragma unroll 4
            for (int kq = 0; kq < 128; ++kq) {
                ulonglong2 wv = *(const ulonglong2*)(Wp + (size_t)kq * (G4 * 4));
                ulonglong2 iv = *(const ulonglong2*)(ibp + 4 * kq);
                FMA2(accA, iv.x, wv.x);
                FMA2(accB, iv.y, wv.y);
            }
            int Jr = l * G4 + crow;
            float a = lo32(accA) + hi32(accA) + lo32(accB) + hi32(accB)
                    + g_part[0][cb][Jr] + g_part[1][cb][Jr]
                    + g_part[2][cb][Jr] + g_part[3][cb][Jr];

            // activation per gate, exchange, cell update
            float act = (q == 2) ? tanhf(a) : (1.f / (1.f + expf(-a)));
            __syncthreads();     // protect sm_g reuse across layers
            sm_g[r16][cb] = act;
            __syncthreads();
            if (q == 0) {
                float gi = act;
                float gf = sm_g[4 + ms][cb];
                float gg = sm_g[8 + ms][cb];
                float go = sm_g[12 + ms][cb];
                float cold = g_c[l][cb][mg];
                float cn = gf * cold + gi * gg;
                g_c[l][cb][mg] = cn;
                g_h[l][cb][mg] = go * tanhf(cn);
            }
            grid_sync();
        }
    }

    // ======== final outputs ========
    const float* hp = &g_h[0][0][0];
    const float* cp = &g_c[0][0][0];
    for (int idx = c * NTHR + tid; idx < L * BATCH * H; idx += NCTA * NTHR) {
        out_h[idx] = hp[idx];
        out_c[idx] = cp[idx];
    }
}

// ---------------- launch ----------------
extern "C" void kernel_launch(void* const* d_in, const int* in_sizes, int n_in,
                              void* d_out, int out_size)
{
    const float* x      = (const float*)d_in[0];
    const float* lin_w  = (const float*)d_in[1];
    const float* lin_b  = (const float*)d_in[2];
    const float* W      = (const float*)d_in[3];
    const float* U      = (const float*)d_in[4];
    const float* G      = (const float*)d_in[5];
    const float* mask_u = (const float*)d_in[6];
    const float* mask_w = (const float*)d_in[7];
    const float* h0     = (const float*)d_in[8];
    const float* c0     = (const float*)d_in[9];
    float* out = (float*)d_out;

    (void)in_sizes; (void)n_in; (void)out_size;

    dim3 tb(32, 8);
    dim3 tg(G4 / 32, LH / 32, L);
    transpose_U<<<tg, tb>>>(U);

    prep_W<<<L * 128, 256>>>(W);

    xp_kernel<<<(TT * BATCH) / 16, 256>>>(x, lin_w, lin_b);

    init_hc<<<64, 256>>>(h0, c0);

    const int smem_bytes = BATCH * ISTR * (int)sizeof(float);  // 66048
    cudaFuncSetAttribute(rnn_kernel, cudaFuncAttributeMaxDynamicSharedMemorySize,
                         smem_bytes);
    rnn_kernel<<<NCTA, NTHR, smem_bytes>>>(G, mask_u, mask_w, out);
}

// round 3
// speedup vs baseline: 1.8861x; 1.0393x over previous
#include <cuda_runtime.h>
#include <math.h>

// Problem constants
#define L    4
#define H    512
#define BATCH 32
#define TT   1024
#define G4   2048        // 4*H gate width per layer
#define LH   2048        // L*H feedback width
#define JTOT 8192        // L * G4 total gate columns
#define NCTA 128
#define NTHR 512
#define ISTR 516         // padded inp_s row stride (floats)

// packed fp32x2 FMA: d = a*b + d  (two fp32 lanes per instruction)
#define FMA2(d, a, b) asm("fma.rn.f32x2 %0, %1, %2, %0;" : "+l"(d) : "l"(a), "l"(b))

__device__ __forceinline__ float lo32(unsigned long long v) { return __uint_as_float((unsigned)v); }
__device__ __forceinline__ float hi32(unsigned long long v) { return __uint_as_float((unsigned)(v >> 32)); }

// ---------------- static device scratch ----------------
// U k-pair interleaved: g_Up[l][k>>1][(j<<1)|(k&1)]
__device__ float g_Up[L][LH / 2][G4 * 2];          // 64MB
// W k-quad interleaved: g_Wz[l][k>>2][row][k&3]
__device__ float g_Wz[L][H / 4][G4][4];            // 16MB
__device__ float g_xp[TT][BATCH][H];               // 64MB
__device__ float g_h[L][BATCH][H];
__device__ float g_c[L][BATCH][H];
__device__ float g_part[4][BATCH][JTOT];           // U-GEMM partials
__device__ unsigned g_cnt = 0;
__device__ volatile unsigned g_gen = 0;

// ---------------- software grid barrier ----------------
__device__ __forceinline__ void grid_sync()
{
    __syncthreads();
    if (threadIdx.x == 0) {
        unsigned g = g_gen;
        __threadfence();
        if (atomicAdd(&g_cnt, 1u) == NCTA - 1u) {
            g_cnt = 0;
            __threadfence();
            g_gen = g + 1u;
        } else {
            while (g_gen == g) { __nanosleep(32); }
        }
        __threadfence();
    }
    __syncthreads();
}

// ---------------- prep kernels ----------------

// g_Up[l][kp][2j + (k&1)] = U[l][j][k]
__global__ void transpose_U(const float* __restrict__ U)
{
    __shared__ float tile[32][33];
    int l  = blockIdx.z;
    int jt = blockIdx.x * 32;
    int kt = blockIdx.y * 32;
    int tx = threadIdx.x, ty = threadIdx.y;      // 32 x 8
    #pragma unroll
    for (int r = 0; r < 32; r += 8)
        tile[ty + r][tx] = U[((size_t)(l * G4 + jt + ty + r)) * LH + kt + tx];
    __syncthreads();
    // write float2 {u(2kp,j), u(2kp+1,j)} at [l][kp][2j]
    int wtid = ty * 32 + tx;                     // 0..255
    int jl = wtid & 31;
    int kp0 = wtid >> 5;                         // 0..7
    #pragma unroll
    for (int r = 0; r < 2; ++r) {
        int kpl = kp0 + r * 8;                   // 0..15
        float2 v = make_float2(tile[jl][2 * kpl], tile[jl][2 * kpl + 1]);
        *(float2*)&g_Up[l][kt / 2 + kpl][(jt + jl) * 2] = v;
    }
}

// g_Wz[l][kq][row][0..3] = W[l][row][4kq..4kq+3]
__global__ void prep_W(const float* __restrict__ W)
{
    int l  = blockIdx.x >> 7;
    int kq = blockIdx.x & 127;
    for (int row = threadIdx.x; row < G4; row += blockDim.x) {
        float4 v = *(const float4*)&W[((size_t)(l * G4 + row)) * H + kq * 4];
        *(float4*)&g_Wz[l][kq][row][0] = v;
    }
}

// Input projection (unchanged)
__global__ void xp_kernel(const float* __restrict__ x,
                          const float* __restrict__ lin_w,
                          const float* __restrict__ lin_b)
{
    __shared__ float xs[16][128];
    int tb0 = blockIdx.x * 16;
    int tid = threadIdx.x;
    #pragma unroll
    for (int r = 0; r < 8; ++r) {
        int e = r * 256 + tid;
        xs[e >> 7][e & 127] = x[(size_t)(tb0 + (e >> 7)) * 128 + (e & 127)];
    }
    __syncthreads();

    int h0 = tid, h1 = tid + 256;
    const float* w0 = lin_w + (size_t)h0 * 128;
    const float* w1 = lin_w + (size_t)h1 * 128;
    float acc0[16], acc1[16];
    #pragma unroll
    for (int p = 0; p < 16; ++p) { acc0[p] = 0.f; acc1[p] = 0.f; }

    for (int i = 0; i < 128; i += 4) {
        float4 a = *(const float4*)(w0 + i);
        float4 b = *(const float4*)(w1 + i);
        #pragma unroll
        for (int p = 0; p < 16; ++p) {
            float4 xv = *(const float4*)&xs[p][i];
            acc0[p] += a.x * xv.x + a.y * xv.y + a.z * xv.z + a.w * xv.w;
            acc1[p] += b.x * xv.x + b.y * xv.y + b.z * xv.z + b.w * xv.w;
        }
    }
    float b0 = lin_b[h0], b1 = lin_b[h1];
    float* xp = &g_xp[0][0][0];
    #pragma unroll
    for (int p = 0; p < 16; ++p) {
        size_t base = (size_t)(tb0 + p) * H;
        xp[base + h0] = acc0[p] + b0;
        xp[base + h1] = acc1[p] + b1;
    }
}

__global__ void init_hc(const float* __restrict__ h0, const float* __restrict__ c0)
{
    float* hp = &g_h[0][0][0];
    float* cp = &g_c[0][0][0];
    for (int i = blockIdx.x * blockDim.x + threadIdx.x; i < L * BATCH * H;
         i += gridDim.x * blockDim.x) {
        hp[i] = h0[i];
        cp[i] = c0[i];
    }
}

// ---------------- persistent recurrent kernel ----------------
__global__ void __launch_bounds__(NTHR, 1)
rnn_kernel(const float* __restrict__ G,
           const float* __restrict__ mask_u,
           const float* __restrict__ mask_w,
           float* __restrict__ out)
{
    extern __shared__ float sm[];                // union: hx[32][512] (B) / inp[32][516] (C)
    __shared__ float red[BATCH][16];
    __shared__ float ghs[BATCH];
    __shared__ float sm_g[16][33];               // gate exchange (activated)

    const int c    = blockIdx.x;
    const int tid  = threadIdx.x;
    const int warp = tid >> 5;
    const int lane = tid & 31;

    // ---- B-phase identity: CTA = (kg, jg); warp = (bw, jw) ----
    const int kg  = c & 3;
    const int jg  = c >> 2;                      // 0..31
    const int J0  = jg * 256;
    const int lU  = J0 >> 11;
    const int jl0 = J0 & 2047;
    const int jw  = warp & 3;
    const int bw  = warp >> 2;
    const int b0w = bw * 8;
    const int c2  = jl0 + jw * 64 + lane * 2;    // within-layer column (pairs)
    const int Jw  = J0 + jw * 64 + lane * 2;     // global column

    // ---- C-phase identity: CTA = mb (h-col block of 4); warp = b-pair ----
    const int mb   = c;                          // 0..127
    const int cb   = warp * 2 + (lane & 1);      // batch 0..31
    const int r16  = lane >> 1;                  // 0..15
    const int q    = r16 >> 2;                   // gate 0..3 (i,f,g,o)
    const int ms   = r16 & 3;
    const int mg   = mb * 4 + ms;                // h index 0..511
    const int crow = q * 512 + mg;               // gate row within layer

    // ---- A-phase identity ----
    const int ab  = tid >> 4;                    // batch 0..31
    const int aks = (tid & 15) * 32;

    float* out_h = out;
    float* out_c = out + L * BATCH * H;
    float* out_g = out + 2 * L * BATCH * H;      // [L][B][T]

    for (int t = 0; t < TT; ++t) {
        // ======== A: build hx slice (layer kg) into sm, stride 512 ========
        {
            const float* hp = &g_h[kg][ab][0];
            const float* mu = &mask_u[(size_t)(kg * BATCH + ab) * H];
            const float* Gp = &G[kg * H];
            float s = 0.f;
            #pragma unroll 4
            for (int kk = 0; kk < 32; ++kk) {
                int k = aks + kk;
                float hm = hp[k] * mu[k];
                sm[ab * 512 + k] = hm;
                s += hm * Gp[k];
            }
            red[ab][tid & 15] = s;
            __syncthreads();
            if (tid < BATCH) {
                float ssum = 0.f;
                #pragma unroll
                for (int r = 0; r < 16; ++r) ssum += red[tid][r];
                float gh = 1.f / (1.f + expf(-ssum));
                ghs[tid] = gh;
                if (jg == 0)
                    out_g[(size_t)(kg * BATCH + tid) * TT + t] = gh;
            }
            __syncthreads();
            float gh = ghs[ab];
            #pragma unroll 4
            for (int kk = 0; kk < 32; ++kk)
                sm[ab * 512 + aks + kk] *= gh;
            __syncthreads();
        }

        // ======== B: U-GEMM partials via fma.rn.f32x2 ========
        {
            unsigned long long acc[8][2];
            #pragma unroll
            for (int i = 0; i < 8; ++i) { acc[i][0] = 0ull; acc[i][1] = 0ull; }

            const float* Ub = &g_Up[lU][kg * 256][c2 * 2];
            #pragma unroll 2
            for (int kp2 = 0; kp2 < 128; ++kp2) {
                ulonglong2 ua = *(const ulonglong2*)(Ub + (size_t)(2 * kp2) * 4096);
                ulonglong2 ub = *(const ulonglong2*)(Ub + (size_t)(2 * kp2 + 1) * 4096);
                #pragma unroll
                for (int i = 0; i < 8; ++i) {
                    ulonglong2 hv = *(const ulonglong2*)&sm[(b0w + i) * 512 + 4 * kp2];
                    FMA2(acc[i][0], hv.x, ua.x);
                    FMA2(acc[i][1], hv.x, ua.y);
                    FMA2(acc[i][0], hv.y, ub.x);
                    FMA2(acc[i][1], hv.y, ub.y);
                }
            }
            #pragma unroll
            for (int i = 0; i < 8; ++i) {
                float2 v = make_float2(lo32(acc[i][0]) + hi32(acc[i][0]),
                                       lo32(acc[i][1]) + hi32(acc[i][1]));
                *(float2*)&g_part[kg][b0w + i][Jw] = v;
            }
        }
        grid_sync();

        // ======== C: serial layer chain ========
        for (int l = 0; l < L; ++l) {
            // build masked inp for all 32 batches (stride ISTR)
            {
                const float* src = (l == 0) ? &g_xp[t][0][0] : &g_h[l - 1][0][0];
                const float* mw  = &mask_w[(size_t)l * BATCH * H];
                #pragma unroll
                for (int r = 0; r < 32; ++r) {
                    int e  = r * NTHR + tid;     // 0..16383
                    int bi = e >> 9, k = e & 511;
                    sm[bi * ISTR + k] = src[(size_t)bi * H + k] * mw[(size_t)bi * H + k];
                }
            }
            __syncthreads();

            // gate dot: row crow, batch cb, K=512 via fma2
            unsigned long long accA = 0ull, accB = 0ull;
            const float* Wp  = &g_Wz[l][0][crow][0];
            const float* ibp = &sm[cb * ISTR];
            #pragma unroll 4
            for (int kq = 0; kq < 128; ++kq) {
                ulonglong2 wv = *(const ulonglong2*)(Wp + (size_t)kq * (G4 * 4));
                ulonglong2 iv = *(const ulonglong2*)(ibp + 4 * kq);
                FMA2(accA, iv.x, wv.x);
                FMA2(accB, iv.y, wv.y);
            }
            int Jr = l * G4 + crow;
            float a = lo32(accA) + hi32(accA) + lo32(accB) + hi32(accB)
                    + g_part[0][cb][Jr] + g_part[1][cb][Jr]
                    + g_part[2][cb][Jr] + g_part[3][cb][Jr];

            // activation per gate, exchange, cell update
            float act = (q == 2) ? tanhf(a) : (1.f / (1.f + expf(-a)));
            __syncthreads();     // protect sm_g reuse across layers
            sm_g[r16][cb] = act;
            __syncthreads();
            if (q == 0) {
                float gi = act;
                float gf = sm_g[4 + ms][cb];
                float gg = sm_g[8 + ms][cb];
                float go = sm_g[12 + ms][cb];
                float cold = g_c[l][cb][mg];
                float cn = gf * cold + gi * gg;
                g_c[l][cb][mg] = cn;
                g_h[l][cb][mg] = go * tanhf(cn);
            }
            grid_sync();
        }
    }

    // ======== final outputs ========
    const float* hp = &g_h[0][0][0];
    const float* cp = &g_c[0][0][0];
    for (int idx = c * NTHR + tid; idx < L * BATCH * H; idx += NCTA * NTHR) {
        out_h[idx] = hp[idx];
        out_c[idx] = cp[idx];
    }
}

// ---------------- launch ----------------
extern "C" void kernel_launch(void* const* d_in, const int* in_sizes, int n_in,
                              void* d_out, int out_size)
{
    const float* x      = (const float*)d_in[0];
    const float* lin_w  = (const float*)d_in[1];
    const float* lin_b  = (const float*)d_in[2];
    const float* W      = (const float*)d_in[3];
    const float* U      = (const float*)d_in[4];
    const float* G      = (const float*)d_in[5];
    const float* mask_u = (const float*)d_in[6];
    const float* mask_w = (const float*)d_in[7];
    const float* h0     = (const float*)d_in[8];
    const float* c0     = (const float*)d_in[9];
    float* out = (float*)d_out;

    (void)in_sizes; (void)n_in; (void)out_size;

    dim3 tb(32, 8);
    dim3 tg(G4 / 32, LH / 32, L);
    transpose_U<<<tg, tb>>>(U);

    prep_W<<<L * 128, 256>>>(W);

    xp_kernel<<<(TT * BATCH) / 16, 256>>>(x, lin_w, lin_b);

    init_hc<<<64, 256>>>(h0, c0);

    const int smem_bytes = BATCH * ISTR * (int)sizeof(float);  // 66048
    cudaFuncSetAttribute(rnn_kernel, cudaFuncAttributeMaxDynamicSharedMemorySize,
                         smem_bytes);
    rnn_kernel<<<NCTA, NTHR, smem_bytes>>>(G, mask_u, mask_w, out);
}

// round 5
// speedup vs baseline: 4.0076x; 2.1248x over previous
#include <cuda_runtime.h>
#include <cuda_bf16.h>
#include <math.h>
#include <stdint.h>

#define L     4
#define H     512
#define BATCH 32
#define TT    1024
#define G4    2048
#define LH    2048
#define JTOT  8192
#define NCTA  128
#define NTHR  512
#define NCHUNK 32          // K=2048 in chunks of 64

#define FMA2(d, a, b) asm("fma.rn.f32x2 %0, %1, %2, %0;" : "+l"(d) : "l"(a), "l"(b))
__device__ __forceinline__ float lo32(unsigned long long v) { return __uint_as_float((unsigned)v); }
__device__ __forceinline__ float hi32(unsigned long long v) { return __uint_as_float((unsigned)(v >> 32)); }

#define SWZ(o) ((unsigned)(o) ^ (((unsigned)(o) >> 3) & 0x70u))

// ---- PTX helpers (base-target features only) ----
__device__ __forceinline__ uint32_t smem_u32(const void* p) {
    uint32_t a;
    asm("{ .reg .u64 t; cvta.to.shared.u64 t, %1; cvt.u32.u64 %0, t; }" : "=r"(a) : "l"(p));
    return a;
}
__device__ __forceinline__ void cp16(uint32_t dst, const void* src) {
    asm volatile("cp.async.cg.shared.global [%0], [%1], 16;" :: "r"(dst), "l"(src) : "memory");
}
#define CP_COMMIT() asm volatile("cp.async.commit_group;" ::: "memory")
#define CP_WAIT(n)  asm volatile("cp.async.wait_group %0;" :: "n"(n) : "memory")

__device__ __forceinline__ void ldsm_x4(uint32_t* r, uint32_t addr) {
    asm volatile("ldmatrix.sync.aligned.m8n8.x4.shared.b16 {%0,%1,%2,%3}, [%4];"
        : "=r"(r[0]), "=r"(r[1]), "=r"(r[2]), "=r"(r[3]) : "r"(addr));
}
__device__ __forceinline__ void mma_bf16(float* d, const uint32_t* a, uint32_t b0, uint32_t b1) {
    asm volatile("mma.sync.aligned.m16n8k16.row.col.f32.bf16.bf16.f32 "
        "{%0,%1,%2,%3}, {%4,%5,%6,%7}, {%8,%9}, {%0,%1,%2,%3};"
        : "+f"(d[0]), "+f"(d[1]), "+f"(d[2]), "+f"(d[3])
        : "r"(a[0]), "r"(a[1]), "r"(a[2]), "r"(a[3]), "r"(b0), "r"(b1));
}

// ---- static scratch ----
__device__ __nv_bfloat16 g_Ubf[2][(size_t)JTOT * LH];   // U hi/lo bf16 [j][k]
__device__ float g_xp[TT][BATCH][H];                    // pre-masked input proj
__device__ float g_h[L][BATCH][H];
__device__ float g_c[L][BATCH][H];
__device__ float g_hin[3][BATCH][H];                    // h * mask_w[l+1]
__device__ __nv_bfloat16 g_hxg[2][BATCH][LH];           // hx hi/lo
__device__ float g_ugemm[BATCH][JTOT];                  // U-GEMM result
__device__ unsigned g_cnt = 0;
__device__ volatile unsigned g_gen = 0;

__device__ __forceinline__ void grid_sync()
{
    __syncthreads();
    if (threadIdx.x == 0) {
        unsigned g = g_gen;
        __threadfence();
        if (atomicAdd(&g_cnt, 1u) == NCTA - 1u) {
            g_cnt = 0;
            __threadfence();
            g_gen = g + 1u;
        } else {
            while (g_gen == g) { __nanosleep(32); }
        }
        __threadfence();
    }
    __syncthreads();
}

// ---- prep ----
__global__ void prep_Ubf(const float* __restrict__ U)
{
    size_t e = ((size_t)blockIdx.x * blockDim.x + threadIdx.x) * 8;
    float4 a = *(const float4*)(U + e);
    float4 b = *(const float4*)(U + e + 4);
    float vs[8] = {a.x, a.y, a.z, a.w, b.x, b.y, b.z, b.w};
    __nv_bfloat16 hb[8], lb[8];
    #pragma unroll
    for (int i = 0; i < 8; ++i) {
        hb[i] = __float2bfloat16(vs[i]);
        lb[i] = __float2bfloat16(vs[i] - __bfloat162float(hb[i]));
    }
    *(uint4*)&g_Ubf[0][e] = *(uint4*)hb;
    *(uint4*)&g_Ubf[1][e] = *(uint4*)lb;
}

__global__ void xp_kernel(const float* __restrict__ x,
                          const float* __restrict__ lin_w,
                          const float* __restrict__ lin_b,
                          const float* __restrict__ mask_w)
{
    __shared__ float xs[16][128];
    int tb0 = blockIdx.x * 16;
    int tid = threadIdx.x;
    #pragma unroll
    for (int r = 0; r < 8; ++r) {
        int e = r * 256 + tid;
        xs[e >> 7][e & 127] = x[(size_t)(tb0 + (e >> 7)) * 128 + (e & 127)];
    }
    __syncthreads();
    int h0 = tid, h1 = tid + 256;
    const float* w0 = lin_w + (size_t)h0 * 128;
    const float* w1 = lin_w + (size_t)h1 * 128;
    float acc0[16], acc1[16];
    #pragma unroll
    for (int p = 0; p < 16; ++p) { acc0[p] = 0.f; acc1[p] = 0.f; }
    for (int i = 0; i < 128; i += 4) {
        float4 a = *(const float4*)(w0 + i);
        float4 b = *(const float4*)(w1 + i);
        #pragma unroll
        for (int p = 0; p < 16; ++p) {
            float4 xv = *(const float4*)&xs[p][i];
            acc0[p] += a.x * xv.x + a.y * xv.y + a.z * xv.z + a.w * xv.w;
            acc1[p] += b.x * xv.x + b.y * xv.y + b.z * xv.z + b.w * xv.w;
        }
    }
    float b0 = lin_b[h0], b1 = lin_b[h1];
    float* xp = &g_xp[0][0][0];
    #pragma unroll
    for (int p = 0; p < 16; ++p) {
        int bb = (tb0 + p) & 31;
        size_t base = (size_t)(tb0 + p) * H;
        xp[base + h0] = (acc0[p] + b0) * mask_w[(size_t)bb * H + h0];
        xp[base + h1] = (acc1[p] + b1) * mask_w[(size_t)bb * H + h1];
    }
}

__global__ void init_hc(const float* __restrict__ h0, const float* __restrict__ c0)
{
    float* hp = &g_h[0][0][0];
    float* cp = &g_c[0][0][0];
    for (int i = blockIdx.x * blockDim.x + threadIdx.x; i < L * BATCH * H;
         i += gridDim.x * blockDim.x)
        { hp[i] = h0[i]; cp[i] = c0[i]; }
}

// ---- persistent kernel ----
// dyn SMEM (1024-aligned):
//   B-phase: ubuf [buf][hl] 4x8KB at 0..32K ; hxbuf [buf][hl] 4x4KB at 32K..48K
//   C-phase reuse: inp 32x516 f at 0 (66048B) ; w_s 16x516 f at 66048 (33024B)
#define SMEM_DYN (99072 + 1024)

__global__ void __launch_bounds__(NTHR, 1)
rnn_kernel(const float* __restrict__ W,
           const float* __restrict__ G,
           const float* __restrict__ mask_u,
           const float* __restrict__ mask_w,
           float* __restrict__ out)
{
    extern __shared__ char smc_raw[];
    __shared__ float redA[16];
    __shared__ float ghA;
    __shared__ float sm_g[16][33];

    const int c    = blockIdx.x;
    const int tid  = threadIdx.x;
    const int wid  = tid >> 5;
    const int lane = tid & 31;

    uint32_t sbr = smem_u32(smc_raw);
    uint32_t sb  = (sbr + 1023u) & ~1023u;
    char* smc = smc_raw + (sb - sbr);
    float* smf = (float*)smc;

    // B-phase warp identity: 4 row-strips x 4 col-strips
    const int rs = wid >> 2;                 // J strip (16 rows)
    const int cs = wid & 3;                  // batch strip (8 cols)
    // A-phase: CTA = (layer, batch)
    const int al  = c & 3;
    const int abt = c >> 2;
    // C-phase: CTA = 4 h-cols; thread = (row r16, batch cb)
    const int cb   = wid * 2 + (lane & 1);
    const int r16  = lane >> 1;
    const int q    = r16 >> 2;
    const int ms   = r16 & 3;
    const int mg   = c * 4 + ms;
    const int crow = q * 512 + mg;

    float* out_h = out;
    float* out_c = out + L * BATCH * H;
    float* out_g = out + 2 * L * BATCH * H;

    for (int t = 0; t < TT; ++t) {
        // ===== A: hx build (one (l,b) per CTA), bf16 hi/lo to global =====
        {
            float hm = g_h[al][abt][tid] * mask_u[((size_t)(al * BATCH + abt)) * H + tid];
            float s  = hm * G[al * H + tid];
            #pragma unroll
            for (int o = 16; o; o >>= 1) s += __shfl_xor_sync(~0u, s, o);
            if (lane == 0) redA[wid] = s;
            __syncthreads();
            if (tid == 0) {
                float ss = 0.f;
                #pragma unroll
                for (int r = 0; r < 16; ++r) ss += redA[r];
                float gh = 1.f / (1.f + expf(-ss));
                ghA = gh;
                out_g[(size_t)(al * BATCH + abt) * TT + t] = gh;
            }
            __syncthreads();
            float v = ghA * hm;
            __nv_bfloat16 hb = __float2bfloat16(v);
            g_hxg[0][abt][al * H + tid] = hb;
            g_hxg[1][abt][al * H + tid] = __float2bfloat16(v - __bfloat162float(hb));
        }
        grid_sync();

        // ===== B: bf16x3 mma.sync U-GEMM, D[64 J x 32 B], K=2048 =====
        {
            float d[4] = {0.f, 0.f, 0.f, 0.f};

            // staging lambda: chunk ck into buffer buf
            auto stage = [&](int ck, int buf) {
                #pragma unroll
                for (int i = 0; i < 2; ++i) {           // U: 1024 x 16B
                    int e = i * NTHR + tid;
                    int hl = e >> 9, r = (e >> 3) & 63, seg = e & 7;
                    const __nv_bfloat16* src =
                        &g_Ubf[hl][((size_t)(c * 64 + r)) * LH + ck * 64 + seg * 8];
                    cp16(sb + buf * 16384 + hl * 8192 + SWZ(r * 128 + seg * 16), src);
                }
                {                                        // hx: 512 x 16B
                    int e = tid;
                    int hl = e >> 8, r = (e >> 3) & 31, seg = e & 7;
                    const __nv_bfloat16* src = &g_hxg[hl][r][ck * 64 + seg * 8];
                    cp16(sb + 32768 + buf * 8192 + hl * 4096 + SWZ(r * 128 + seg * 16), src);
                }
            };

            stage(0, 0);
            CP_COMMIT();
            for (int ck = 0; ck < NCHUNK; ++ck) {
                if (ck < NCHUNK - 1) {
                    stage(ck + 1, (ck + 1) & 1);
                    CP_COMMIT();
                    CP_WAIT(1);
                } else {
                    CP_WAIT(0);
                }
                __syncthreads();

                uint32_t au = sb + (ck & 1) * 16384;
                uint32_t bu = sb + 32768 + (ck & 1) * 8192;
                #pragma unroll
                for (int s2 = 0; s2 < 2; ++s2) {
                    uint32_t baddr = (cs * 8 + (lane & 7)) * 128 + s2 * 64 + (lane >> 3) * 16;
                    uint32_t bh[4], bl_[4];
                    ldsm_x4(bh,  bu + SWZ(baddr));
                    ldsm_x4(bl_, bu + 4096 + SWZ(baddr));
                    #pragma unroll
                    for (int sh = 0; sh < 2; ++sh) {
                        int s = s2 * 2 + sh;
                        uint32_t aaddr = (rs * 16 + (lane & 15)) * 128 + s * 32 + (lane >> 4) * 16;
                        uint32_t ah[4], al_[4];
                        ldsm_x4(ah,  au + SWZ(aaddr));
                        ldsm_x4(al_, au + 8192 + SWZ(aaddr));
                        mma_bf16(d, ah,  bh[2 * sh], bh[2 * sh + 1]);
                        mma_bf16(d, ah,  bl_[2 * sh], bl_[2 * sh + 1]);
                        mma_bf16(d, al_, bh[2 * sh], bh[2 * sh + 1]);
                    }
                }
                __syncthreads();
            }

            // writeback D: thread holds rows (m, m+8), cols (n, n+1)
            int m = c * 64 + rs * 16 + (lane >> 2);
            int n = cs * 8 + (lane & 3) * 2;
            g_ugemm[n][m]         = d[0];
            g_ugemm[n + 1][m]     = d[1];
            g_ugemm[n][m + 8]     = d[2];
            g_ugemm[n + 1][m + 8] = d[3];
        }
        grid_sync();

        // ===== C: serial layer chain =====
        float* w_s = smf + 32 * 516;         // 16 x 516 floats
        for (int l = 0; l < L; ++l) {
            const float* src = (l == 0) ? &g_xp[t][0][0] : &g_hin[l - 1][0][0];
            #pragma unroll
            for (int i = 0; i < 8; ++i) {    // inp: 32x512 floats
                int e = i * NTHR + tid;      // 0..4095 float4
                int bi = e >> 7, ks = e & 127;
                *(float4*)&smf[bi * 516 + ks * 4] = *(const float4*)&src[bi * 512 + ks * 4];
            }
            #pragma unroll
            for (int i = 0; i < 4; ++i) {    // W rows: 16x512 floats
                int e = i * NTHR + tid;      // 0..2047 float4
                int rl = e >> 7, ks = e & 127;
                int rowg = (rl >> 2) * 512 + c * 4 + (rl & 3);
                *(float4*)&w_s[rl * 516 + ks * 4] =
                    *(const float4*)&W[((size_t)(l * G4 + rowg)) * H + ks * 4];
            }
            __syncthreads();

            unsigned long long accA = 0ull, accB = 0ull;
            const float* wp = &w_s[r16 * 516];
            const float* ip = &smf[cb * 516];
            #pragma unroll 4
            for (int kq = 0; kq < 128; ++kq) {
                ulonglong2 wv = *(const ulonglong2*)(wp + 4 * kq);
                ulonglong2 iv = *(const ulonglong2*)(ip + 4 * kq);
                FMA2(accA, iv.x, wv.x);
                FMA2(accB, iv.y, wv.y);
            }
            int Jr = l * G4 + crow;
            float a = lo32(accA) + hi32(accA) + lo32(accB) + hi32(accB)
                    + g_ugemm[cb][Jr];

            float act = (q == 2) ? tanhf(a) : (1.f / (1.f + expf(-a)));
            __syncthreads();
            sm_g[r16][cb] = act;
            __syncthreads();
            if (q == 0) {
                float gf = sm_g[4 + ms][cb];
                float gg = sm_g[8 + ms][cb];
                float go = sm_g[12 + ms][cb];
                float cold = g_c[l][cb][mg];
                float cn = gf * cold + act * gg;
                float hy = go * tanhf(cn);
                g_c[l][cb][mg] = cn;
                g_h[l][cb][mg] = hy;
                if (l < 3)
                    g_hin[l][cb][mg] = hy * mask_w[((size_t)((l + 1) * BATCH + cb)) * H + mg];
            }
            grid_sync();
        }
    }

    const float* hp = &g_h[0][0][0];
    const float* cp = &g_c[0][0][0];
    for (int idx = c * NTHR + tid; idx < L * BATCH * H; idx += NCTA * NTHR) {
        out_h[idx] = hp[idx];
        out_c[idx] = cp[idx];
    }
}

// ---- launch ----
extern "C" void kernel_launch(void* const* d_in, const int* in_sizes, int n_in,
                              void* d_out, int out_size)
{
    const float* x      = (const float*)d_in[0];
    const float* lin_w  = (const float*)d_in[1];
    const float* lin_b  = (const float*)d_in[2];
    const float* W      = (const float*)d_in[3];
    const float* U      = (const float*)d_in[4];
    const float* G      = (const float*)d_in[5];
    const float* mask_u = (const float*)d_in[6];
    const float* mask_w = (const float*)d_in[7];
    const float* h0     = (const float*)d_in[8];
    const float* c0     = (const float*)d_in[9];
    float* out = (float*)d_out;
    (void)in_sizes; (void)n_in; (void)out_size;

    prep_Ubf<<<8192, 256>>>(U);
    xp_kernel<<<(TT * BATCH) / 16, 256>>>(x, lin_w, lin_b, mask_w);
    init_hc<<<64, 256>>>(h0, c0);

    cudaFuncSetAttribute(rnn_kernel, cudaFuncAttributeMaxDynamicSharedMemorySize, SMEM_DYN);
    rnn_kernel<<<NCTA, NTHR, SMEM_DYN>>>(W, G, mask_u, mask_w, out);
}

// round 6
// speedup vs baseline: 5.1443x; 1.2836x over previous
#include <cuda_runtime.h>
#include <cuda_bf16.h>
#include <math.h>
#include <stdint.h>

#define L     4
#define H     512
#define BATCH 32
#define TT    1024
#define G4    2048
#define LH    2048
#define JTOT  8192
#define NCTA  128
#define NTHR  512

#define SWZ(o) ((unsigned)(o) ^ (((unsigned)(o) >> 3) & 0x70u))

// ---- PTX helpers (base-target features only) ----
__device__ __forceinline__ uint32_t smem_u32(const void* p) {
    uint32_t a;
    asm("{ .reg .u64 t; cvta.to.shared.u64 t, %1; cvt.u32.u64 %0, t; }" : "=r"(a) : "l"(p));
    return a;
}
__device__ __forceinline__ void cp16(uint32_t dst, const void* src) {
    asm volatile("cp.async.cg.shared.global [%0], [%1], 16;" :: "r"(dst), "l"(src) : "memory");
}
#define CP_COMMIT() asm volatile("cp.async.commit_group;" ::: "memory")
#define CP_WAIT(n)  asm volatile("cp.async.wait_group %0;" :: "n"(n) : "memory")

__device__ __forceinline__ void ldsm_x4(uint32_t* r, uint32_t addr) {
    asm volatile("ldmatrix.sync.aligned.m8n8.x4.shared.b16 {%0,%1,%2,%3}, [%4];"
        : "=r"(r[0]), "=r"(r[1]), "=r"(r[2]), "=r"(r[3]) : "r"(addr));
}
__device__ __forceinline__ void mma_bf16(float* d, const uint32_t* a, uint32_t b0, uint32_t b1) {
    asm volatile("mma.sync.aligned.m16n8k16.row.col.f32.bf16.bf16.f32 "
        "{%0,%1,%2,%3}, {%4,%5,%6,%7}, {%8,%9}, {%0,%1,%2,%3};"
        : "+f"(d[0]), "+f"(d[1]), "+f"(d[2]), "+f"(d[3])
        : "r"(a[0]), "r"(a[1]), "r"(a[2]), "r"(a[3]), "r"(b0), "r"(b1));
}
__device__ __forceinline__ void wait_cnt(const unsigned* p, unsigned target) {
    unsigned v;
    do {
        asm volatile("ld.acquire.gpu.u32 %0, [%1];" : "=r"(v) : "l"(p) : "memory");
    } while (v < target);
}

// ---- static device scratch ----
// prebuilt SMEM-image layouts (blocked-atom + SW128), all bf16 hi/lo:
__device__ __align__(16) char g_Uimg[(size_t)128 * 16 * 2 * 16384];  // [c][chunk][hl] 16KB each (64 rows x 256B)
__device__ __align__(16) char g_Wimg[(size_t)4 * 128 * 2 * 16384];   // [l][c][hl] 16KB each (16 rows x 1024B)
__device__ __align__(16) char g_xpimg[(size_t)TT * 2 * 32768];       // [t][hl] 32KB each (32 rows x 1024B)
__device__ __align__(16) char g_hinimg[(size_t)3 * 2 * 32768];       // [l][hl]
__device__ __align__(16) char g_hximg[(size_t)16 * 2 * 8192];        // [chunk][hl] (32 rows x 256B)
__device__ float g_h[L][BATCH][H];
__device__ float g_c[L][BATCH][H];
__device__ float g_ugemm[BATCH][JTOT];
__device__ unsigned g_cntA[4] = {0, 0, 0, 0};
__device__ unsigned g_cnt = 0;
__device__ volatile unsigned g_gen = 0;

// ---- software grid barrier ----
__device__ __forceinline__ void grid_sync()
{
    __syncthreads();
    if (threadIdx.x == 0) {
        unsigned g = g_gen;
        __threadfence();
        if (atomicAdd(&g_cnt, 1u) == NCTA - 1u) {
            g_cnt = 0;
            __threadfence();
            g_gen = g + 1u;
        } else {
            while (g_gen == g) { }
        }
        __threadfence();
    }
    __syncthreads();
}

// ---- prep kernels ----

// U -> per-(CTA, chunk) 16KB swizzled images, bf16 hi/lo
__global__ void prep_U_img(const float* __restrict__ U)
{
    int blk = blockIdx.x;                 // c*16 + chunk
    int c = blk >> 4, chunk = blk & 15;
    char* dsth = g_Uimg + ((size_t)blk * 2) * 16384;
    char* dstl = dsth + 16384;
    for (int i = threadIdx.x; i < 1024; i += 256) {
        int r = i >> 4, s8 = i & 15;      // 64 rows x 16 segs(16B)
        const float* src = U + ((size_t)(c * 64 + r)) * LH + chunk * 128 + s8 * 8;
        __nv_bfloat16 hb[8], lb[8];
        #pragma unroll
        for (int j = 0; j < 8; ++j) {
            float v = src[j];
            hb[j] = __float2bfloat16(v);
            lb[j] = __float2bfloat16(v - __bfloat162float(hb[j]));
        }
        unsigned byte = SWZ((unsigned)((r >> 3) * 1024 + (s8 >> 3) * 8192 +
                                       (r & 7) * 128 + (s8 & 7) * 16));
        *(uint4*)(dsth + byte) = *(uint4*)hb;
        *(uint4*)(dstl + byte) = *(uint4*)lb;
    }
}

// W -> per-(layer, CTA) 16KB images, rows permuted (q, ms)
__global__ void prep_W_img(const float* __restrict__ W)
{
    int blk = blockIdx.x;                 // l*128 + c
    int l = blk >> 7, c = blk & 127;
    char* dsth = g_Wimg + ((size_t)blk * 2) * 16384;
    char* dstl = dsth + 16384;
    for (int i = threadIdx.x; i < 1024; i += 256) {
        int r = i >> 6, s8 = i & 63;      // 16 rows x 64 segs
        int q = r >> 2, ms = r & 3;
        int wrow = q * 512 + c * 4 + ms;
        const float* src = W + ((size_t)(l * G4 + wrow)) * H + s8 * 8;
        __nv_bfloat16 hb[8], lb[8];
        #pragma unroll
        for (int j = 0; j < 8; ++j) {
            float v = src[j];
            hb[j] = __float2bfloat16(v);
            lb[j] = __float2bfloat16(v - __bfloat162float(hb[j]));
        }
        unsigned byte = SWZ((unsigned)((r >> 3) * 1024 + (s8 >> 3) * 2048 +
                                       (r & 7) * 128 + (s8 & 7) * 16));
        *(uint4*)(dsth + byte) = *(uint4*)hb;
        *(uint4*)(dstl + byte) = *(uint4*)lb;
    }
}

// input projection -> masked, bf16 hi/lo, written directly into per-t images
__global__ void xp_kernel(const float* __restrict__ x,
                          const float* __restrict__ lin_w,
                          const float* __restrict__ lin_b,
                          const float* __restrict__ mask_w)
{
    __shared__ float xs[16][128];
    int tb0 = blockIdx.x * 16;
    int tid = threadIdx.x;
    #pragma unroll
    for (int r = 0; r < 8; ++r) {
        int e = r * 256 + tid;
        xs[e >> 7][e & 127] = x[(size_t)(tb0 + (e >> 7)) * 128 + (e & 127)];
    }
    __syncthreads();
    int h0 = tid, h1 = tid + 256;
    const float* w0 = lin_w + (size_t)h0 * 128;
    const float* w1 = lin_w + (size_t)h1 * 128;
    float acc0[16], acc1[16];
    #pragma unroll
    for (int p = 0; p < 16; ++p) { acc0[p] = 0.f; acc1[p] = 0.f; }
    for (int i = 0; i < 128; i += 4) {
        float4 a = *(const float4*)(w0 + i);
        float4 b = *(const float4*)(w1 + i);
        #pragma unroll
        for (int p = 0; p < 16; ++p) {
            float4 xv = *(const float4*)&xs[p][i];
            acc0[p] += a.x * xv.x + a.y * xv.y + a.z * xv.z + a.w * xv.w;
            acc1[p] += b.x * xv.x + b.y * xv.y + b.z * xv.z + b.w * xv.w;
        }
    }
    float b0 = lin_b[h0], b1 = lin_b[h1];
    #pragma unroll
    for (int p = 0; p < 16; ++p) {
        int tb = tb0 + p;
        int tt = tb >> 5, bb = tb & 31;
        char* base = g_xpimg + (size_t)tt * 65536;
        #pragma unroll
        for (int cc = 0; cc < 2; ++cc) {
            int hh = cc ? h1 : h0;
            float v = ((cc ? acc1[p] : acc0[p]) + (cc ? b1 : b0)) *
                      mask_w[(size_t)bb * H + hh];
            __nv_bfloat16 hb = __float2bfloat16(v);
            __nv_bfloat16 lb = __float2bfloat16(v - __bfloat162float(hb));
            int seg = hh >> 3;
            unsigned byte = SWZ((unsigned)((bb >> 3) * 1024 + (seg >> 3) * 4096 +
                                           (bb & 7) * 128 + (seg & 7) * 16 + (hh & 7) * 2));
            *(__nv_bfloat16*)(base + byte) = hb;
            *(__nv_bfloat16*)(base + 32768 + byte) = lb;
        }
    }
}

__global__ void init_hc(const float* __restrict__ h0, const float* __restrict__ c0)
{
    if (blockIdx.x == 0 && threadIdx.x < 4) g_cntA[threadIdx.x] = 0;
    float* hp = &g_h[0][0][0];
    float* cp = &g_c[0][0][0];
    for (int i = blockIdx.x * blockDim.x + threadIdx.x; i < L * BATCH * H;
         i += gridDim.x * blockDim.x)
        { hp[i] = h0[i]; cp[i] = c0[i]; }
}

// ---- persistent kernel ----
// dyn SMEM (1024-aligned base), union:
//  B-phase: Ubuf[buf][hl] 2x32KB @0 ; hxbuf[buf][hl] 2x16KB @65536
//  C-phase: inp[hl] 64KB @0 ; Wbuf[buf][hl] 2x32KB @65536
#define SMEM_DYN (131072 + 1024)

__global__ void __launch_bounds__(NTHR, 1)
rnn_kernel(const float* __restrict__ G,
           const float* __restrict__ mask_u,
           const float* __restrict__ mask_w,
           float* __restrict__ out)
{
    extern __shared__ char smc_raw[];
    __shared__ float redA[16];
    __shared__ float ghA;
    __shared__ float sm_g[16][33];
    __shared__ float red[4][16][33];

    const int c    = blockIdx.x;
    const int tid  = threadIdx.x;
    const int wid  = tid >> 5;
    const int lane = tid & 31;

    uint32_t sbr = smem_u32(smc_raw);
    uint32_t sb  = (sbr + 1023u) & ~1023u;

    // A-phase identity: CTA = (layer, batch)
    const int al  = c & 3;
    const int abt = c >> 2;
    // B-phase warp identity: 4 J strips x 4 batch strips
    const int rs = wid >> 2;
    const int cs = wid & 3;
    // C-phase warp identity: (K-split, batch strip)
    const int ks = wid >> 2;
    const int ns = wid & 3;
    // C-phase thread identity
    const int cb   = wid * 2 + (lane & 1);
    const int r16  = lane >> 1;
    const int q    = r16 >> 2;
    const int ms   = r16 & 3;
    const int mg   = c * 4 + ms;
    const int crow = q * 512 + mg;

    float* out_h = out;
    float* out_c = out + L * BATCH * H;
    float* out_g = out + 2 * L * BATCH * H;

    for (int t = 0; t < TT; ++t) {
        // ===== A: hx build for this CTA's (al, abt), write swizzled bf16 image =====
        {
            float hm = g_h[al][abt][tid] * mask_u[((size_t)(al * BATCH + abt)) * H + tid];
            float s  = hm * G[al * H + tid];
            #pragma unroll
            for (int o = 16; o; o >>= 1) s += __shfl_xor_sync(~0u, s, o);
            if (lane == 0) redA[wid] = s;
            __syncthreads();
            if (tid == 0) {
                float ss = 0.f;
                #pragma unroll
                for (int r = 0; r < 16; ++r) ss += redA[r];
                float gh = 1.f / (1.f + expf(-ss));
                ghA = gh;
                out_g[(size_t)(al * BATCH + abt) * TT + t] = gh;
            }
            __syncthreads();
            float v = ghA * hm;
            __nv_bfloat16 hb = __float2bfloat16(v);
            __nv_bfloat16 lb = __float2bfloat16(v - __bfloat162float(hb));
            int kg = al * 512 + tid;
            int chunk = kg >> 7, kl = kg & 127, seg = kl >> 3;
            unsigned byte = SWZ((unsigned)((abt >> 3) * 1024 + (seg >> 3) * 4096 +
                                           (abt & 7) * 128 + (seg & 7) * 16 + (kl & 7) * 2));
            char* base = g_hximg + (size_t)chunk * 16384;
            *(__nv_bfloat16*)(base + byte) = hb;
            *(__nv_bfloat16*)(base + 8192 + byte) = lb;
            __syncthreads();
            if (tid == 0) {
                __threadfence();
                atomicAdd(&g_cntA[al], 1u);
            }
        }

        // ===== B: U-GEMM (bf16x3 mma.sync), D[64 J x 32 B], K=2048, chunks of 128 =====
        {
            const unsigned targ = 32u * (unsigned)(t + 1);
            float d[4] = {0.f, 0.f, 0.f, 0.f};

            auto stageB = [&](int ck) {
                int buf = ck & 1;
                const char* us = g_Uimg + ((size_t)(c * 16 + ck) * 2) * 16384;
                #pragma unroll
                for (int i = 0; i < 4; ++i) {
                    int idx = i * 512 + tid;
                    cp16(sb + buf * 32768 + idx * 16, us + idx * 16);
                }
                const char* hs = g_hximg + (size_t)ck * 2 * 8192;
                #pragma unroll
                for (int i = 0; i < 2; ++i) {
                    int idx = i * 512 + tid;
                    cp16(sb + 65536 + buf * 16384 + idx * 16, hs + idx * 16);
                }
            };

            wait_cnt(&g_cntA[0], targ);
            stageB(0);
            CP_COMMIT();
            for (int ck = 0; ck < 16; ++ck) {
                if (ck < 15) {
                    if (((ck + 1) & 3) == 0) wait_cnt(&g_cntA[(ck + 1) >> 2], targ);
                    stageB(ck + 1);
                    CP_COMMIT();
                    CP_WAIT(1);
                } else {
                    CP_WAIT(0);
                }
                __syncthreads();

                uint32_t auh = sb + (ck & 1) * 32768, aul = auh + 16384;
                uint32_t buh = sb + 65536 + (ck & 1) * 16384, bul = buh + 8192;
                #pragma unroll
                for (int g = 0; g < 4; ++g) {
                    uint32_t baddr = (g >> 1) * 4096 + (cs * 8 + (lane & 7)) * 128 +
                                     (g & 1) * 64 + (lane >> 3) * 16;
                    uint32_t bh[4], bl_[4];
                    ldsm_x4(bh,  buh + SWZ(baddr));
                    ldsm_x4(bl_, bul + SWZ(baddr));
                    #pragma unroll
                    for (int sh = 0; sh < 2; ++sh) {
                        int s = g * 2 + sh;
                        uint32_t aaddr = (s >> 2) * 8192 + (rs * 16 + (lane & 15)) * 128 +
                                         (s & 3) * 32 + (lane >> 4) * 16;
                        uint32_t ah[4], al_[4];
                        ldsm_x4(ah,  auh + SWZ(aaddr));
                        ldsm_x4(al_, aul + SWZ(aaddr));
                        mma_bf16(d, ah,  bh[2 * sh],  bh[2 * sh + 1]);
                        mma_bf16(d, ah,  bl_[2 * sh], bl_[2 * sh + 1]);
                        mma_bf16(d, al_, bh[2 * sh],  bh[2 * sh + 1]);
                    }
                }
                __syncthreads();
            }
            int m = c * 64 + rs * 16 + (lane >> 2);
            int n = cs * 8 + (lane & 3) * 2;
            g_ugemm[n][m]         = d[0];
            g_ugemm[n + 1][m]     = d[1];
            g_ugemm[n][m + 8]     = d[2];
            g_ugemm[n + 1][m + 8] = d[3];
        }
        grid_sync();

        // ===== C: serial layer chain, W-GEMM on mma.sync =====
        #pragma unroll
        for (int l = 0; l < 4; ++l) {
            const char* isrc = (l == 0) ? (g_xpimg + (size_t)t * 65536)
                                        : (g_hinimg + (size_t)(l - 1) * 65536);
            #pragma unroll
            for (int i = 0; i < 8; ++i) {       // inp hi/lo 64KB
                int idx = i * 512 + tid;
                cp16(sb + idx * 16, isrc + idx * 16);
            }
            if (l == 0) {                        // W0 32KB (not prefetched)
                const char* wsrc = g_Wimg + ((size_t)c * 2) * 16384;
                #pragma unroll
                for (int i = 0; i < 4; ++i) {
                    int idx = i * 512 + tid;
                    cp16(sb + 65536 + idx * 16, wsrc + idx * 16);
                }
            }
            CP_COMMIT();
            if (l < 3) {                         // prefetch W(l+1)
                const char* wsrc = g_Wimg + ((size_t)((l + 1) * 128 + c) * 2) * 16384;
                uint32_t wdst = sb + 65536 + ((l + 1) & 1) * 32768;
                #pragma unroll
                for (int i = 0; i < 4; ++i) {
                    int idx = i * 512 + tid;
                    cp16(wdst + idx * 16, wsrc + idx * 16);
                }
                CP_COMMIT();
                CP_WAIT(1);
            } else {
                CP_WAIT(0);
            }
            __syncthreads();

            float ug = g_ugemm[cb][l * G4 + crow];

            float dd[4] = {0.f, 0.f, 0.f, 0.f};
            uint32_t wh = sb + 65536 + (l & 1) * 32768, wl = wh + 16384;
            uint32_t ih = sb, il = sb + 32768;
            #pragma unroll
            for (int gg = 0; gg < 4; ++gg) {
                uint32_t baddr = (ks * 2 + (gg >> 1)) * 4096 + (ns * 8 + (lane & 7)) * 128 +
                                 (gg & 1) * 64 + (lane >> 3) * 16;
                uint32_t bh[4], bl_[4];
                ldsm_x4(bh,  ih + SWZ(baddr));
                ldsm_x4(bl_, il + SWZ(baddr));
                #pragma unroll
                for (int jh = 0; jh < 2; ++jh) {
                    int s = ks * 8 + gg * 2 + jh;
                    uint32_t aaddr = (s >> 2) * 2048 + (lane & 15) * 128 +
                                     (s & 3) * 32 + (lane >> 4) * 16;
                    uint32_t ah[4], al_[4];
                    ldsm_x4(ah,  wh + SWZ(aaddr));
                    ldsm_x4(al_, wl + SWZ(aaddr));
                    mma_bf16(dd, ah,  bh[2 * jh],  bh[2 * jh + 1]);
                    mma_bf16(dd, ah,  bl_[2 * jh], bl_[2 * jh + 1]);
                    mma_bf16(dd, al_, bh[2 * jh],  bh[2 * jh + 1]);
                }
            }
            {
                int m0 = lane >> 2, n0 = ns * 8 + (lane & 3) * 2;
                red[ks][m0][n0]         = dd[0];
                red[ks][m0][n0 + 1]     = dd[1];
                red[ks][m0 + 8][n0]     = dd[2];
                red[ks][m0 + 8][n0 + 1] = dd[3];
            }
            __syncthreads();

            float a = red[0][r16][cb] + red[1][r16][cb] +
                      red[2][r16][cb] + red[3][r16][cb] + ug;
            float act = (q == 2) ? tanhf(a) : (1.f / (1.f + expf(-a)));
            sm_g[r16][cb] = act;
            __syncthreads();
            if (q == 0) {
                float gf  = sm_g[4 + ms][cb];
                float gg_ = sm_g[8 + ms][cb];
                float go  = sm_g[12 + ms][cb];
                float cold = g_c[l][cb][mg];
                float cn = gf * cold + act * gg_;
                float hy = go * tanhf(cn);
                g_c[l][cb][mg] = cn;
                g_h[l][cb][mg] = hy;
                if (l < 3) {
                    float hv = hy * mask_w[((size_t)((l + 1) * BATCH + cb)) * H + mg];
                    __nv_bfloat16 hb = __float2bfloat16(hv);
                    __nv_bfloat16 lb = __float2bfloat16(hv - __bfloat162float(hb));
                    int seg = mg >> 3;
                    unsigned byte = SWZ((unsigned)((cb >> 3) * 1024 + (seg >> 3) * 4096 +
                                                   (cb & 7) * 128 + (seg & 7) * 16 + (mg & 7) * 2));
                    char* base = g_hinimg + (size_t)l * 65536;
                    *(__nv_bfloat16*)(base + byte) = hb;
                    *(__nv_bfloat16*)(base + 32768 + byte) = lb;
                }
            }
            grid_sync();
        }
    }

    const float* hp = &g_h[0][0][0];
    const float* cp = &g_c[0][0][0];
    for (int idx = c * NTHR + tid; idx < L * BATCH * H; idx += NCTA * NTHR) {
        out_h[idx] = hp[idx];
        out_c[idx] = cp[idx];
    }
}

// ---- launch ----
extern "C" void kernel_launch(void* const* d_in, const int* in_sizes, int n_in,
                              void* d_out, int out_size)
{
    const float* x      = (const float*)d_in[0];
    const float* lin_w  = (const float*)d_in[1];
    const float* lin_b  = (const float*)d_in[2];
    const float* W      = (const float*)d_in[3];
    const float* U      = (const float*)d_in[4];
    const float* G      = (const float*)d_in[5];
    const float* mask_u = (const float*)d_in[6];
    const float* mask_w = (const float*)d_in[7];
    const float* h0     = (const float*)d_in[8];
    const float* c0     = (const float*)d_in[9];
    float* out = (float*)d_out;
    (void)in_sizes; (void)n_in; (void)out_size;

    prep_U_img<<<128 * 16, 256>>>(U);
    prep_W_img<<<4 * 128, 256>>>(W);
    xp_kernel<<<(TT * BATCH) / 16, 256>>>(x, lin_w, lin_b, mask_w);
    init_hc<<<64, 256>>>(h0, c0);

    cudaFuncSetAttribute(rnn_kernel, cudaFuncAttributeMaxDynamicSharedMemorySize, SMEM_DYN);
    rnn_kernel<<<NCTA, NTHR, SMEM_DYN>>>(G, mask_u, mask_w, out);
}